// round 16
// baseline (speedup 1.0000x reference)
#include <cuda_runtime.h>
#include <math.h>

#define D 128
#define H 4
#define NMAX 500000
#define BMAX 8192
#define ROWS_CAP 256
#define NT 256          // 8 warps
#define KREG 4          // register-resident rows per warp (covers n < 32)

// Global scratch (fallback path only) + segment starts.
__device__ float4 g_scores[NMAX];
__device__ int    g_seg_start[BMAX + 1];

// ---------------------------------------------------------------------------
// Dtype-agnostic ids (reference claims int64 but JAX x64-off gives int32).
// ---------------------------------------------------------------------------
__device__ __forceinline__ bool ids_are_64bit(const int* ids32, int N) {
    int j = ((N - 1) & 1) ? (N - 1) : (N - 2);
    if (j < 0) j = 0;
    return ids32[j] == 0;
}
__device__ __forceinline__ int get_id_raw(const void* ids, bool is64, int n) {
    return is64 ? (int)((const long long*)ids)[n] : ((const int*)ids)[n];
}

__global__ void k_bounds(const void* __restrict__ ids, int N, int B) {
    int b = blockIdx.x * blockDim.x + threadIdx.x;
    if (b > B) return;
    bool is64 = ids_are_64bit((const int*)ids, N);
    int lo = 0, hi = N;
    while (lo < hi) {
        int mid = (lo + hi) >> 1;
        if (get_id_raw(ids, is64, mid) < b) lo = mid + 1; else hi = mid;
    }
    g_seg_start[b] = lo;
}

__device__ __forceinline__ float dot4(float4 a, float4 w) {
    return a.x * w.x + a.y * w.y + a.z * w.z + a.w * w.w;
}

// Single-row 4-head reduction (6 shuffles). Lane l -> head (l&3) full sum.
__device__ __forceinline__ float reduce4_heads(float s0, float s1, float s2,
                                               float s3, int lane) {
    const unsigned FULL = 0xFFFFFFFFu;
    float a01_send = (lane & 1) ? s0 : s1;
    float a01 = ((lane & 1) ? s1 : s0) + __shfl_xor_sync(FULL, a01_send, 1);
    float a23_send = (lane & 1) ? s2 : s3;
    float a23 = ((lane & 1) ? s3 : s2) + __shfl_xor_sync(FULL, a23_send, 1);
    float b_send = (lane & 2) ? a01 : a23;
    float v = ((lane & 2) ? a23 : a01) + __shfl_xor_sync(FULL, b_send, 2);
    v += __shfl_xor_sync(FULL, v, 4);
    v += __shfl_xor_sync(FULL, v, 8);
    v += __shfl_xor_sync(FULL, v, 16);
    return v;
}

// TWO-row 8-value reduction (9 shuffles / 2 rows). Lane l -> full sum of
// row ((l>>2)&1), head (l&3).
__device__ __forceinline__ float reduce8_2rows(
    float p0, float p1, float p2, float p3,
    float p4, float p5, float p6, float p7, int lane)
{
    const unsigned FULL = 0xFFFFFFFFu;
    float s;
    s = (lane & 1) ? p0 : p1; float q0 = ((lane & 1) ? p1 : p0) + __shfl_xor_sync(FULL, s, 1);
    s = (lane & 1) ? p2 : p3; float q1 = ((lane & 1) ? p3 : p2) + __shfl_xor_sync(FULL, s, 1);
    s = (lane & 1) ? p4 : p5; float q2 = ((lane & 1) ? p5 : p4) + __shfl_xor_sync(FULL, s, 1);
    s = (lane & 1) ? p6 : p7; float q3 = ((lane & 1) ? p7 : p6) + __shfl_xor_sync(FULL, s, 1);
    s = (lane & 2) ? q0 : q1; float r0 = ((lane & 2) ? q1 : q0) + __shfl_xor_sync(FULL, s, 2);
    s = (lane & 2) ? q2 : q3; float r1 = ((lane & 2) ? q3 : q2) + __shfl_xor_sync(FULL, s, 2);
    s = (lane & 4) ? r0 : r1; float v = ((lane & 4) ? r1 : r0) + __shfl_xor_sync(FULL, s, 4);
    v += __shfl_xor_sync(FULL, v, 8);
    v += __shfl_xor_sync(FULL, v, 16);
    return v;
}

// ---------------------------------------------------------------------------
// Fused kernel: block per segment, online softmax, TWO barriers total.
// After bar1 each warp redundantly reduces S, then does attn-write +
// weight derivation + pooling for its own rows using register-held e/xr.
// smem: e_s[ROWS_CAP*4] | w_s[ROWS_CAP] | pool4[8*32]f4 | wredS[8*4] | Rsh[4]
// ---------------------------------------------------------------------------
__global__ void __launch_bounds__(NT, 4) k_fused(
    const float* __restrict__ x,
    const float* __restrict__ W,
    const float* __restrict__ bias,
    const float* __restrict__ temp,
    float* __restrict__ out_pooled,   // [B, D]
    float* __restrict__ out_attn,     // [H, N]
    int N, int B)
{
    extern __shared__ float sdyn[];
    float*  e_f   = sdyn;                          // ROWS_CAP*4
    float4* e_4   = (float4*)sdyn;
    float*  w_s   = sdyn + ROWS_CAP * 4;           // ROWS_CAP (fallback only)
    float4* pool4 = (float4*)(w_s + ROWS_CAP);     // 8*32 float4
    float*  wredS = (float*)(pool4 + 8 * 32);      // 8 warps x 4 heads
    float*  Rsh   = wredS + 32;                    // 4 (fallback only)

    int b = blockIdx.x;
    if (b >= B) return;
    int start = g_seg_start[b];
    int len   = g_seg_start[b + 1] - start;
    int tid   = threadIdx.x;
    int lane  = tid & 31, warp = tid >> 5;
    const unsigned FULL = 0xFFFFFFFFu;

    float4 w0 = ((const float4*)W)[lane];
    float4 w1 = ((const float4*)W)[32 + lane];
    float4 w2 = ((const float4*)W)[64 + lane];
    float4 w3 = ((const float4*)W)[96 + lane];
    float  b_l  = bias[lane & 3];
    float  tinv = 1.0f / temp[0];

    const float4* xg4 = (const float4*)(x + (size_t)start * D);

    if (len <= ROWS_CAP) {
        // ---- prefetch KREG rows per warp (MLP=4) ----
        float4 xr[KREG];
        #pragma unroll
        for (int k = 0; k < KREG; k++) {
            int n = warp + k * 8;
            if (n < len) xr[k] = xg4[n * 32 + lane];
        }

        // ---- scores + exp + per-head S; e kept in registers (no STS) ----
        float S_acc = 0.f;
        float e_reg[KREG / 2];
        #pragma unroll
        for (int k = 0; k < KREG; k += 2) {
            int n0 = warp + k * 8, n1 = n0 + 8;
            float e = 0.f;
            if (n1 < len) {
                float4 xa = xr[k], xb = xr[k + 1];
                float v = reduce8_2rows(
                    dot4(xa, w0), dot4(xa, w1), dot4(xa, w2), dot4(xa, w3),
                    dot4(xb, w0), dot4(xb, w1), dot4(xb, w2), dot4(xb, w3),
                    lane);
                e = __expf((v + b_l) * tinv);
                S_acc += e;
            } else if (n0 < len) {
                float4 xa = xr[k];
                float v = reduce4_heads(dot4(xa, w0), dot4(xa, w1),
                                        dot4(xa, w2), dot4(xa, w3), lane);
                e = __expf((v + b_l) * tinv);
                if (!(lane & 4)) S_acc += e;
            }
            e_reg[k / 2] = e;
        }
        // tail rows (n >= 32): e goes to smem for the post-R pass
        for (int n = warp + KREG * 8; n < len; n += 16) {
            int n1 = n + 8;
            if (n1 < len) {
                float4 xa = xg4[n * 32 + lane];
                float4 xb = xg4[n1 * 32 + lane];
                float v = reduce8_2rows(
                    dot4(xa, w0), dot4(xa, w1), dot4(xa, w2), dot4(xa, w3),
                    dot4(xb, w0), dot4(xb, w1), dot4(xb, w2), dot4(xb, w3),
                    lane);
                float e = __expf((v + b_l) * tinv);
                S_acc += e;
                if (lane < 8) e_f[(n + ((lane & 4) << 1)) * 4 + (lane & 3)] = e;
            } else {
                float4 xa = xg4[n * 32 + lane];
                float v = reduce4_heads(dot4(xa, w0), dot4(xa, w1),
                                        dot4(xa, w2), dot4(xa, w3), lane);
                float e = __expf((v + b_l) * tinv);
                if (!(lane & 4)) S_acc += e;
                if (lane < 4) e_f[n * 4 + lane] = e;
            }
        }
        S_acc += __shfl_xor_sync(FULL, S_acc, 4);
        if (lane < 4) wredS[warp * 4 + lane] = S_acc;
        __syncthreads();                                        // bar 1

        // ---- every warp reduces S itself (no second barrier) ----
        // wredS[w*4+h]: lane l holds (w=l>>2, h=l&3); sum over w via xor 4/8/16.
        float Sl = wredS[lane];
        Sl += __shfl_xor_sync(FULL, Sl, 4);
        Sl += __shfl_xor_sync(FULL, Sl, 8);
        Sl += __shfl_xor_sync(FULL, Sl, 16);
        float Rm = 1.0f / Sl;                      // head (lane&3)
        int g = lane & ~3;
        float R0 = __shfl_sync(FULL, Rm, g);
        float R1 = __shfl_sync(FULL, Rm, g + 1);
        float R2 = __shfl_sync(FULL, Rm, g + 2);
        float R3 = __shfl_sync(FULL, Rm, g + 3);

        float* attn0 = out_attn + start;
        float4 acc = make_float4(0.f, 0.f, 0.f, 0.f);

        // ---- register rows: attn write + weight + pooling, all in-warp ----
        #pragma unroll
        for (int k = 0; k < KREG; k += 2) {
            int n0 = warp + k * 8, n1 = n0 + 8;
            if (n1 < len) {
                float t = e_reg[k / 2] * Rm;           // attn (head l&3, parity row)
                if (lane < 8)
                    attn0[(size_t)(lane & 3) * N + n0 + ((lane & 4) << 1)] = t;
                float u = t + __shfl_xor_sync(FULL, t, 1);
                u += __shfl_xor_sync(FULL, u, 2);
                float wp = 0.25f * u;                  // weight of my parity row
                float wo = __shfl_xor_sync(FULL, wp, 4);
                float wr0 = (lane & 4) ? wo : wp;      // row n0
                float wr1 = (lane & 4) ? wp : wo;      // row n1
                acc.x += wr0 * xr[k].x + wr1 * xr[k + 1].x;
                acc.y += wr0 * xr[k].y + wr1 * xr[k + 1].y;
                acc.z += wr0 * xr[k].z + wr1 * xr[k + 1].z;
                acc.w += wr0 * xr[k].w + wr1 * xr[k + 1].w;
            } else if (n0 < len) {
                float t = e_reg[k / 2] * Rm;
                if (lane < 4)
                    attn0[(size_t)lane * N + n0] = t;
                float u = t + __shfl_xor_sync(FULL, t, 1);
                u += __shfl_xor_sync(FULL, u, 2);
                float w = 0.25f * u;
                acc.x += w * xr[k].x; acc.y += w * xr[k].y;
                acc.z += w * xr[k].z; acc.w += w * xr[k].w;
            }
        }
        // ---- tail rows: e from smem, x re-read (L1-hit) ----
        for (int n = warp + KREG * 8; n < len; n += 8) {
            float4 e4 = e_4[n];
            float w = 0.25f * (e4.x * R0 + e4.y * R1 + e4.z * R2 + e4.w * R3);
            float4 v = xg4[n * 32 + lane];
            acc.x += w * v.x; acc.y += w * v.y;
            acc.z += w * v.z; acc.w += w * v.w;
            if (lane < 4) {
                float t = e4.x * R0;
                t = (lane == 1) ? e4.y * R1 : t;
                t = (lane == 2) ? e4.z * R2 : t;
                t = (lane == 3) ? e4.w * R3 : t;
                attn0[(size_t)lane * N + n] = t;
            }
        }

        pool4[warp * 32 + lane] = acc;
        __syncthreads();                                        // bar 2
        if (warp == 0) {
            float4 r = pool4[lane];
            #pragma unroll
            for (int p = 1; p < 8; p++) {
                float4 t = pool4[p * 32 + lane];
                r.x += t.x; r.y += t.y; r.z += t.z; r.w += t.w;
            }
            ((float4*)(out_pooled + (size_t)b * D))[lane] = r;
        }
        return;
    }

    // ================= fallback (len > ROWS_CAP), online scheme ============
    {
        float S_acc = 0.f;
        for (int n = warp; n < len; n += 8) {
            float4 xv = xg4[n * 32 + lane];
            float v = reduce4_heads(dot4(xv, w0), dot4(xv, w1),
                                    dot4(xv, w2), dot4(xv, w3), lane);
            float e = __expf((v + b_l) * tinv);
            S_acc += e;
            if (lane < 4)
                ((float*)&g_scores[start + n])[lane] = e;
        }
        if (lane < 4) wredS[warp * 4 + lane] = S_acc;
        __syncthreads();
        if (tid < 4) {
            float s = 0.f;
            #pragma unroll
            for (int w = 0; w < 8; w++) s += wredS[w * 4 + tid];
            Rsh[tid] = 1.0f / s;
        }
        __syncthreads();

        float4 Rv = *(float4*)Rsh;
        for (int i = tid; i < len; i += NT) {
            float4 e = g_scores[start + i];
            float a0 = e.x * Rv.x, a1 = e.y * Rv.y;
            float a2 = e.z * Rv.z, a3 = e.w * Rv.w;
            size_t p = (size_t)start + i;
            out_attn[p]                 = a0;
            out_attn[(size_t)N + p]     = a1;
            out_attn[2 * (size_t)N + p] = a2;
            out_attn[3 * (size_t)N + p] = a3;
            g_scores[start + i].x = 0.25f * (a0 + a1 + a2 + a3);
        }
        __syncthreads();

        float4 acc = make_float4(0.f, 0.f, 0.f, 0.f);
        for (int n = warp; n < len; n += 8) {
            float wj = g_scores[start + n].x;
            float4 v = xg4[n * 32 + lane];
            acc.x += wj * v.x; acc.y += wj * v.y;
            acc.z += wj * v.z; acc.w += wj * v.w;
        }
        pool4[warp * 32 + lane] = acc;
        __syncthreads();
        if (warp == 0) {
            float4 r = pool4[lane];
            #pragma unroll
            for (int p = 1; p < 8; p++) {
                float4 t = pool4[p * 32 + lane];
                r.x += t.x; r.y += t.y; r.z += t.z; r.w += t.w;
            }
            ((float4*)(out_pooled + (size_t)b * D))[lane] = r;
        }
    }
}

// ---------------------------------------------------------------------------
extern "C" void kernel_launch(void* const* d_in, const int* in_sizes, int n_in,
                              void* d_out, int out_size)
{
    const float* x    = (const float*)d_in[0];
    const void*  ids  = d_in[1];
    const float* W    = (const float*)d_in[2];
    const float* bias = (const float*)d_in[3];
    const float* temp = (const float*)d_in[4];

    int N = in_sizes[1];
    int B = (out_size - H * N) / D;
    if (B < 1) B = 1;
    if (B > BMAX) B = BMAX;

    float* out_pooled = (float*)d_out;                   // [B, D]
    float* out_attn   = (float*)d_out + (size_t)B * D;   // [H, N]

    const int SMEM = (ROWS_CAP * 4 + ROWS_CAP + 8 * 32 * 4 + 32 + 4) * 4;

    k_bounds<<<(B + 256) / 256, 256>>>(ids, N, B);
    k_fused<<<B, NT, SMEM>>>(x, W, bias, temp, out_pooled, out_attn, N, B);
}

// round 17
// speedup vs baseline: 1.0928x; 1.0928x over previous
#include <cuda_runtime.h>
#include <math.h>

#define D 128
#define H 4
#define NMAX 500000
#define BMAX 8192
#define ROWS_CAP 256
#define NT 256          // 8 warps
#define KREG 4          // register-resident rows per warp (covers n < 32)

// Global scratch (fallback path only) + segment starts.
__device__ float4 g_scores[NMAX];
__device__ int    g_seg_start[BMAX + 1];

// ---------------------------------------------------------------------------
// Dtype-agnostic ids (reference claims int64 but JAX x64-off gives int32).
// ---------------------------------------------------------------------------
__device__ __forceinline__ bool ids_are_64bit(const int* ids32, int N) {
    int j = ((N - 1) & 1) ? (N - 1) : (N - 2);
    if (j < 0) j = 0;
    return ids32[j] == 0;
}
__device__ __forceinline__ int get_id_raw(const void* ids, bool is64, int n) {
    return is64 ? (int)((const long long*)ids)[n] : ((const int*)ids)[n];
}

__global__ void k_bounds(const void* __restrict__ ids, int N, int B) {
    int b = blockIdx.x * blockDim.x + threadIdx.x;
    if (b > B) return;
    bool is64 = ids_are_64bit((const int*)ids, N);
    int lo = 0, hi = N;
    while (lo < hi) {
        int mid = (lo + hi) >> 1;
        if (get_id_raw(ids, is64, mid) < b) lo = mid + 1; else hi = mid;
    }
    g_seg_start[b] = lo;
}

__device__ __forceinline__ float dot4(float4 a, float4 w) {
    return a.x * w.x + a.y * w.y + a.z * w.z + a.w * w.w;
}

// Single-row 4-head reduction (6 shuffles). Lane l -> head (l&3) full sum.
__device__ __forceinline__ float reduce4_heads(float s0, float s1, float s2,
                                               float s3, int lane) {
    const unsigned FULL = 0xFFFFFFFFu;
    float a01_send = (lane & 1) ? s0 : s1;
    float a01 = ((lane & 1) ? s1 : s0) + __shfl_xor_sync(FULL, a01_send, 1);
    float a23_send = (lane & 1) ? s2 : s3;
    float a23 = ((lane & 1) ? s3 : s2) + __shfl_xor_sync(FULL, a23_send, 1);
    float b_send = (lane & 2) ? a01 : a23;
    float v = ((lane & 2) ? a23 : a01) + __shfl_xor_sync(FULL, b_send, 2);
    v += __shfl_xor_sync(FULL, v, 4);
    v += __shfl_xor_sync(FULL, v, 8);
    v += __shfl_xor_sync(FULL, v, 16);
    return v;
}

// TWO-row 8-value reduction (9 shuffles / 2 rows). Lane l -> full sum of
// row ((l>>2)&1), head (l&3).
__device__ __forceinline__ float reduce8_2rows(
    float p0, float p1, float p2, float p3,
    float p4, float p5, float p6, float p7, int lane)
{
    const unsigned FULL = 0xFFFFFFFFu;
    float s;
    s = (lane & 1) ? p0 : p1; float q0 = ((lane & 1) ? p1 : p0) + __shfl_xor_sync(FULL, s, 1);
    s = (lane & 1) ? p2 : p3; float q1 = ((lane & 1) ? p3 : p2) + __shfl_xor_sync(FULL, s, 1);
    s = (lane & 1) ? p4 : p5; float q2 = ((lane & 1) ? p5 : p4) + __shfl_xor_sync(FULL, s, 1);
    s = (lane & 1) ? p6 : p7; float q3 = ((lane & 1) ? p7 : p6) + __shfl_xor_sync(FULL, s, 1);
    s = (lane & 2) ? q0 : q1; float r0 = ((lane & 2) ? q1 : q0) + __shfl_xor_sync(FULL, s, 2);
    s = (lane & 2) ? q2 : q3; float r1 = ((lane & 2) ? q3 : q2) + __shfl_xor_sync(FULL, s, 2);
    s = (lane & 4) ? r0 : r1; float v = ((lane & 4) ? r1 : r0) + __shfl_xor_sync(FULL, s, 4);
    v += __shfl_xor_sync(FULL, v, 8);
    v += __shfl_xor_sync(FULL, v, 16);
    return v;
}

// ---------------------------------------------------------------------------
// Fused kernel (block per segment, online softmax, pair-row reduction,
// software-pipelined tail loads).
// smem: e_s[ROWS_CAP*4] | w_s[ROWS_CAP] | pool4[8*32]f4 | wredS[8*4] | Rsh[4]
// ---------------------------------------------------------------------------
__global__ void __launch_bounds__(NT, 4) k_fused(
    const float* __restrict__ x,
    const float* __restrict__ W,
    const float* __restrict__ bias,
    const float* __restrict__ temp,
    float* __restrict__ out_pooled,   // [B, D]
    float* __restrict__ out_attn,     // [H, N]
    int N, int B)
{
    extern __shared__ float sdyn[];
    float*  e_f   = sdyn;                          // ROWS_CAP*4
    float4* e_4   = (float4*)sdyn;
    float*  w_s   = sdyn + ROWS_CAP * 4;           // ROWS_CAP
    float4* pool4 = (float4*)(w_s + ROWS_CAP);     // 8*32 float4
    float*  wredS = (float*)(pool4 + 8 * 32);      // 8 warps x 4 heads
    float*  Rsh   = wredS + 32;                    // 4

    int b = blockIdx.x;
    if (b >= B) return;
    int start = g_seg_start[b];
    int len   = g_seg_start[b + 1] - start;
    int tid   = threadIdx.x;
    int lane  = tid & 31, warp = tid >> 5;
    const unsigned FULL = 0xFFFFFFFFu;

    float4 w0 = ((const float4*)W)[lane];
    float4 w1 = ((const float4*)W)[32 + lane];
    float4 w2 = ((const float4*)W)[64 + lane];
    float4 w3 = ((const float4*)W)[96 + lane];
    float  b_l  = bias[lane & 3];
    float  tinv = 1.0f / temp[0];

    const float4* xg4 = (const float4*)(x + (size_t)start * D);

    if (len <= ROWS_CAP) {
        // ---- prefetch KREG rows per warp (MLP=4) ----
        float4 xr[KREG];
        #pragma unroll
        for (int k = 0; k < KREG; k++) {
            int n = warp + k * 8;
            if (n < len) xr[k] = xg4[n * 32 + lane];
        }

        // ---- scores + exp + inline per-head S (pair-row reductions) ----
        float S_acc = 0.f;
        #pragma unroll
        for (int k = 0; k < KREG; k += 2) {
            int n0 = warp + k * 8, n1 = n0 + 8;
            if (n1 < len) {
                float4 xa = xr[k], xb = xr[k + 1];
                float v = reduce8_2rows(
                    dot4(xa, w0), dot4(xa, w1), dot4(xa, w2), dot4(xa, w3),
                    dot4(xb, w0), dot4(xb, w1), dot4(xb, w2), dot4(xb, w3),
                    lane);
                float e = __expf((v + b_l) * tinv);
                S_acc += e;
                if (lane < 8) e_f[(n0 + ((lane & 4) << 1)) * 4 + (lane & 3)] = e;
            } else if (n0 < len) {
                float4 xa = xr[k];
                float v = reduce4_heads(dot4(xa, w0), dot4(xa, w1),
                                        dot4(xa, w2), dot4(xa, w3), lane);
                float e = __expf((v + b_l) * tinv);
                if (!(lane & 4)) S_acc += e;
                if (lane < 4) e_f[n0 * 4 + lane] = e;
            }
        }
        // ---- tail rows (n >= 32): software-pipelined pair loads ----
        {
            int n = warp + KREG * 8;
            if (n < len) {
                const float4* pa = xg4 + n * 32 + lane;
                float4 xa = *pa;
                bool hb = (n + 8) < len;
                float4 xb;
                if (hb) xb = *(pa + 256);              // +8 rows
                while (true) {
                    int nn = n + 16;
                    bool hnext = nn < len;
                    bool hnb = false;
                    float4 ya, yb;
                    if (hnext) {                        // preload next pair
                        const float4* pn = pa + 512;    // +16 rows
                        ya = *pn;
                        hnb = (nn + 8) < len;
                        if (hnb) yb = *(pn + 256);
                    }
                    if (hb) {
                        float v = reduce8_2rows(
                            dot4(xa, w0), dot4(xa, w1), dot4(xa, w2), dot4(xa, w3),
                            dot4(xb, w0), dot4(xb, w1), dot4(xb, w2), dot4(xb, w3),
                            lane);
                        float e = __expf((v + b_l) * tinv);
                        S_acc += e;
                        if (lane < 8) e_f[(n + ((lane & 4) << 1)) * 4 + (lane & 3)] = e;
                    } else {
                        float v = reduce4_heads(dot4(xa, w0), dot4(xa, w1),
                                                dot4(xa, w2), dot4(xa, w3), lane);
                        float e = __expf((v + b_l) * tinv);
                        if (!(lane & 4)) S_acc += e;
                        if (lane < 4) e_f[n * 4 + lane] = e;
                    }
                    if (!hnext) break;
                    xa = ya; xb = yb; hb = hnb; n = nn; pa += 512;
                }
            }
        }
        S_acc += __shfl_xor_sync(FULL, S_acc, 4);
        if (lane < 4) wredS[warp * 4 + lane] = S_acc;
        __syncthreads();                                        // bar 1

        // ---- tiny cross-warp S reduce (4 threads) ----
        if (tid < 4) {
            float s = 0.f;
            #pragma unroll
            for (int w = 0; w < 8; w++) s += wredS[w * 4 + tid];
            Rsh[tid] = (len > 0) ? 1.0f / s : 0.f;
        }
        __syncthreads();                                        // bar 2

        // ---- attn output + per-node mean weight ----
        float4 Rv = *(float4*)Rsh;
        if (tid < len) {
            float4 e = e_4[tid];
            float a0 = e.x * Rv.x, a1 = e.y * Rv.y;
            float a2 = e.z * Rv.z, a3 = e.w * Rv.w;
            size_t p = (size_t)start + tid;
            out_attn[p]                 = a0;
            out_attn[(size_t)N + p]     = a1;
            out_attn[2 * (size_t)N + p] = a2;
            out_attn[3 * (size_t)N + p] = a3;
            w_s[tid] = 0.25f * (a0 + a1 + a2 + a3);
        }
        __syncthreads();                                        // bar 3

        // ---- pooling: register rows free; tail rows batched L1-hit loads ----
        float4 acc = make_float4(0.f, 0.f, 0.f, 0.f);
        #pragma unroll
        for (int k = 0; k < KREG; k++) {
            int n = warp + k * 8;
            if (n < len) {
                float wj = w_s[n];
                acc.x += wj * xr[k].x; acc.y += wj * xr[k].y;
                acc.z += wj * xr[k].z; acc.w += wj * xr[k].w;
            }
        }
        for (int n = warp + KREG * 8; n < len; n += 16) {
            int n1 = n + 8;
            float4 v0 = xg4[n * 32 + lane];
            float wj0 = w_s[n];
            if (n1 < len) {
                float4 v1 = xg4[n1 * 32 + lane];
                float wj1 = w_s[n1];
                acc.x += wj0 * v0.x + wj1 * v1.x;
                acc.y += wj0 * v0.y + wj1 * v1.y;
                acc.z += wj0 * v0.z + wj1 * v1.z;
                acc.w += wj0 * v0.w + wj1 * v1.w;
            } else {
                acc.x += wj0 * v0.x; acc.y += wj0 * v0.y;
                acc.z += wj0 * v0.z; acc.w += wj0 * v0.w;
            }
        }
        pool4[warp * 32 + lane] = acc;
        __syncthreads();                                        // bar 4
        if (warp == 0) {
            float4 r = pool4[lane];
            #pragma unroll
            for (int p = 1; p < 8; p++) {
                float4 t = pool4[p * 32 + lane];
                r.x += t.x; r.y += t.y; r.z += t.z; r.w += t.w;
            }
            ((float4*)(out_pooled + (size_t)b * D))[lane] = r;
        }
        return;
    }

    // ================= fallback (len > ROWS_CAP), online scheme ============
    {
        float S_acc = 0.f;
        for (int n = warp; n < len; n += 8) {
            float4 xv = xg4[n * 32 + lane];
            float v = reduce4_heads(dot4(xv, w0), dot4(xv, w1),
                                    dot4(xv, w2), dot4(xv, w3), lane);
            float e = __expf((v + b_l) * tinv);
            S_acc += e;
            if (lane < 4)
                ((float*)&g_scores[start + n])[lane] = e;
        }
        if (lane < 4) wredS[warp * 4 + lane] = S_acc;
        __syncthreads();
        if (tid < 4) {
            float s = 0.f;
            #pragma unroll
            for (int w = 0; w < 8; w++) s += wredS[w * 4 + tid];
            Rsh[tid] = 1.0f / s;
        }
        __syncthreads();

        float4 Rv = *(float4*)Rsh;
        for (int i = tid; i < len; i += NT) {
            float4 e = g_scores[start + i];
            float a0 = e.x * Rv.x, a1 = e.y * Rv.y;
            float a2 = e.z * Rv.z, a3 = e.w * Rv.w;
            size_t p = (size_t)start + i;
            out_attn[p]                 = a0;
            out_attn[(size_t)N + p]     = a1;
            out_attn[2 * (size_t)N + p] = a2;
            out_attn[3 * (size_t)N + p] = a3;
            g_scores[start + i].x = 0.25f * (a0 + a1 + a2 + a3);
        }
        __syncthreads();

        float4 acc = make_float4(0.f, 0.f, 0.f, 0.f);
        for (int n = warp; n < len; n += 8) {
            float wj = g_scores[start + n].x;
            float4 v = xg4[n * 32 + lane];
            acc.x += wj * v.x; acc.y += wj * v.y;
            acc.z += wj * v.z; acc.w += wj * v.w;
        }
        pool4[warp * 32 + lane] = acc;
        __syncthreads();
        if (warp == 0) {
            float4 r = pool4[lane];
            #pragma unroll
            for (int p = 1; p < 8; p++) {
                float4 t = pool4[p * 32 + lane];
                r.x += t.x; r.y += t.y; r.z += t.z; r.w += t.w;
            }
            ((float4*)(out_pooled + (size_t)b * D))[lane] = r;
        }
    }
}

// ---------------------------------------------------------------------------
extern "C" void kernel_launch(void* const* d_in, const int* in_sizes, int n_in,
                              void* d_out, int out_size)
{
    const float* x    = (const float*)d_in[0];
    const void*  ids  = d_in[1];
    const float* W    = (const float*)d_in[2];
    const float* bias = (const float*)d_in[3];
    const float* temp = (const float*)d_in[4];

    int N = in_sizes[1];
    int B = (out_size - H * N) / D;
    if (B < 1) B = 1;
    if (B > BMAX) B = BMAX;

    float* out_pooled = (float*)d_out;                   // [B, D]
    float* out_attn   = (float*)d_out + (size_t)B * D;   // [H, N]

    const int SMEM = (ROWS_CAP * 4 + ROWS_CAP + 8 * 32 * 4 + 32 + 4) * 4;

    k_bounds<<<(B + 256) / 256, 256>>>(ids, N, B);
    k_fused<<<B, NT, SMEM>>>(x, W, bias, temp, out_pooled, out_attn, N, B);
}